// round 1
// baseline (speedup 1.0000x reference)
#include <cuda_runtime.h>

typedef unsigned long long u64;

#define CB  2048
#define CT  512
#define CI  64
#define CH  32
#define CG  128
#define CBH 1024   // CB/2

// 512 MB scratch for input projections, stored as f32x2 pairs over batch:
// g_xg[(t*CBH + b/2)*CG + g] = {xg[t][b_even][g], xg[t][b_odd][g]}
__device__ u64 g_xg[(size_t)CT * CBH * CG];

__device__ __forceinline__ u64 ffma2(u64 a, u64 b, u64 c) {
    u64 d;
    asm("fma.rn.f32x2 %0, %1, %2, %3;" : "=l"(d) : "l"(a), "l"(b), "l"(c));
    return d;
}
__device__ __forceinline__ u64 pack2(float lo, float hi) {
    u64 d;
    asm("mov.b64 %0, {%1, %2};" : "=l"(d) : "f"(lo), "f"(hi));
    return d;
}
__device__ __forceinline__ float2 unpack2(u64 v) {
    float2 r;
    asm("mov.b64 {%0, %1}, %2;" : "=f"(r.x), "=f"(r.y) : "l"(v));
    return r;
}

// ---------------------------------------------------------------------------
// K1: input projection GEMM.  xg[t][b][g] = sum_k x[b][t][k] * W_ih[g][k] + bias[g]
// Block: 256 threads, tile = 128 batch rows x 128 gates, K=64 (not tiled).
// Thread tile: 8 rows x 8 gates, f32x2-paired along rows (batch).
// ---------------------------------------------------------------------------
#define WTS 132  // padded smem row stride (floats); 132*4 % 16 == 0 keeps 16B alignment

extern __shared__ float sm1[];

__global__ __launch_bounds__(256, 2) void k1_inproj(
    const float* __restrict__ x, const float* __restrict__ Wih,
    const float* __restrict__ bih, const float* __restrict__ bhh)
{
    float* Wt = sm1;              // Wt[k*WTS + g]
    float* xs = sm1 + 64 * WTS;   // xs[k*WTS + r]
    const int tid = threadIdx.x;
    const int t   = blockIdx.y;
    const int bt  = blockIdx.x * 128;

    // Stage W_ih transposed: Wt[k][g]
    #pragma unroll
    for (int idx = tid; idx < CG * CI; idx += 256) {
        int g = idx >> 6, k = idx & 63;
        Wt[k * WTS + g] = Wih[idx];
    }
    // Stage x tile transposed: xs[k][r], r = batch row within tile (t fixed)
    #pragma unroll
    for (int idx = tid; idx < 128 * CI; idx += 256) {
        int r = idx >> 6, k = idx & 63;
        xs[k * WTS + r] = x[((size_t)(bt + r) * CT + t) * CI + k];
    }
    __syncthreads();

    const int tx = tid & 15, ty = tid >> 4;
    const int g0 = tx * 8, r0 = ty * 8;

    u64 acc[8][4];
    #pragma unroll
    for (int g = 0; g < 8; g++) {
        float bs = bih[g0 + g] + bhh[g0 + g];
        u64 bd = pack2(bs, bs);
        #pragma unroll
        for (int p = 0; p < 4; p++) acc[g][p] = bd;
    }

    #pragma unroll 4
    for (int k = 0; k < CI; k++) {
        const ulonglong2 xa = *(const ulonglong2*)&xs[k * WTS + r0];
        const ulonglong2 xb = *(const ulonglong2*)&xs[k * WTS + r0 + 4];
        const float4 wa = *(const float4*)&Wt[k * WTS + g0];
        const float4 wb = *(const float4*)&Wt[k * WTS + g0 + 4];
        u64 xp[4] = {xa.x, xa.y, xb.x, xb.y};
        u64 wd[8] = {pack2(wa.x, wa.x), pack2(wa.y, wa.y),
                     pack2(wa.z, wa.z), pack2(wa.w, wa.w),
                     pack2(wb.x, wb.x), pack2(wb.y, wb.y),
                     pack2(wb.z, wb.z), pack2(wb.w, wb.w)};
        #pragma unroll
        for (int g = 0; g < 8; g++) {
            #pragma unroll
            for (int p = 0; p < 4; p++)
                acc[g][p] = ffma2(xp[p], wd[g], acc[g][p]);
        }
    }

    // Store pairs: acc[g][p] = {row r0+2p, row r0+2p+1}
    #pragma unroll
    for (int p = 0; p < 4; p++) {
        int bp = ((bt + r0) >> 1) + p;
        u64* dst = &g_xg[((size_t)t * CBH + bp) * CG + g0];
        #pragma unroll
        for (int g = 0; g < 8; g += 2) {
            ulonglong2 v;
            v.x = acc[g][p];
            v.y = acc[g + 1][p];
            *(ulonglong2*)(dst + g) = v;
        }
    }
}

// ---------------------------------------------------------------------------
// K2: recurrence. One warp per 4 batch elements, thread j = hidden unit j.
// Gate order (PyTorch/ref): 0=i, 1=f, 2=g(tanh), 3=o ; row = gate*32 + j.
// Weights in smem as Whs[k][j][gate] -> one LDS.128 per k per thread.
// h staged in smem as hs[k] = {h_b0[k], h_b1[k], h_b2[k], h_b3[k]} (float4).
// ---------------------------------------------------------------------------
#define WHS 132  // padded stride (floats), 16B-aligned rows

__device__ __forceinline__ float sigmf(float v) {
    return __fdividef(1.f, 1.f + __expf(-v));
}
__device__ __forceinline__ float tanhf_fast(float v) {
    // 1 - 2/(1+exp(2v)) : monotone, no inf-inf at extremes, ~1e-6 abs err
    return 1.f - __fdividef(2.f, 1.f + __expf(2.f * v));
}
__device__ __forceinline__ void lstm_cell(float gi, float gf, float gg, float go,
                                          float& c, float& h) {
    float iv = sigmf(gi);
    float fv = sigmf(gf);
    float gv = tanhf_fast(gg);
    float ov = sigmf(go);
    c = fv * c + iv * gv;
    h = ov * tanhf_fast(c);
}

__global__ __launch_bounds__(32) void k2_rnn(
    const float* __restrict__ Whh, const float* __restrict__ wfc,
    const float* __restrict__ bfc, float* __restrict__ out)
{
    __shared__ float      Whs[CH * WHS];  // [k][j*4 + gate]
    __shared__ ulonglong2 hs[CH];         // hs[k] = 4 batch h-values of unit k

    const int j   = threadIdx.x;           // hidden unit
    const int b0  = blockIdx.x * 4;        // first batch element
    const int bp0 = blockIdx.x * 2;        // first batch-pair index

    // Stage W_hh: Whs[k][j'][g] = W_hh[(g*32+j')*32 + k]
    for (int idx = j; idx < CG * CH; idx += 32) {
        int row = idx >> 5, k = idx & 31;
        Whs[k * WHS + (row & 31) * 4 + (row >> 5)] = Whh[idx];
    }
    *(float4*)&hs[j] = make_float4(0.f, 0.f, 0.f, 0.f);
    float c[4] = {0.f, 0.f, 0.f, 0.f};
    float h[4] = {0.f, 0.f, 0.f, 0.f};
    const float wfcv = wfc[j];
    __syncwarp();

    // Prefetch xg for t=0
    u64 xgc[2][4];
    #pragma unroll
    for (int p = 0; p < 2; p++)
        #pragma unroll
        for (int g = 0; g < 4; g++)
            xgc[p][g] = g_xg[((size_t)(bp0 + p)) * CG + g * CH + j];

    for (int t = 0; t < CT; t++) {
        // Prefetch next timestep's input projections (hidden by k-loop)
        u64 xgn[2][4];
        if (t + 1 < CT) {
            #pragma unroll
            for (int p = 0; p < 2; p++)
                #pragma unroll
                for (int g = 0; g < 4; g++)
                    xgn[p][g] = g_xg[((size_t)(t + 1) * CBH + bp0 + p) * CG + g * CH + j];
        }

        u64 acc[2][4];
        #pragma unroll
        for (int p = 0; p < 2; p++)
            #pragma unroll
            for (int g = 0; g < 4; g++)
                acc[p][g] = xgc[p][g];

        #pragma unroll
        for (int k = 0; k < CH; k++) {
            const float4 w4 = *(const float4*)&Whs[k * WHS + j * 4];
            const ulonglong2 h4 = hs[k];  // {hb0,hb1} , {hb2,hb3}
            u64 w0 = pack2(w4.x, w4.x);
            u64 w1 = pack2(w4.y, w4.y);
            u64 w2 = pack2(w4.z, w4.z);
            u64 w3 = pack2(w4.w, w4.w);
            acc[0][0] = ffma2(h4.x, w0, acc[0][0]);
            acc[0][1] = ffma2(h4.x, w1, acc[0][1]);
            acc[0][2] = ffma2(h4.x, w2, acc[0][2]);
            acc[0][3] = ffma2(h4.x, w3, acc[0][3]);
            acc[1][0] = ffma2(h4.y, w0, acc[1][0]);
            acc[1][1] = ffma2(h4.y, w1, acc[1][1]);
            acc[1][2] = ffma2(h4.y, w2, acc[1][2]);
            acc[1][3] = ffma2(h4.y, w3, acc[1][3]);
        }
        __syncwarp();  // all lanes done reading hs(t)

        #pragma unroll
        for (int p = 0; p < 2; p++) {
            float2 gi = unpack2(acc[p][0]);
            float2 gf = unpack2(acc[p][1]);
            float2 gg = unpack2(acc[p][2]);
            float2 go = unpack2(acc[p][3]);
            lstm_cell(gi.x, gf.x, gg.x, go.x, c[2 * p],     h[2 * p]);
            lstm_cell(gi.y, gf.y, gg.y, go.y, c[2 * p + 1], h[2 * p + 1]);
        }
        *(float4*)&hs[j] = make_float4(h[0], h[1], h[2], h[3]);
        __syncwarp();  // hs(t+1) visible before next iteration reads

        #pragma unroll
        for (int p = 0; p < 2; p++)
            #pragma unroll
            for (int g = 0; g < 4; g++)
                xgc[p][g] = xgn[p][g];
    }

    // Fused fc: out[b] = sum_j h[b][j] * W_fc[0][j] + b_fc
    #pragma unroll
    for (int bi = 0; bi < 4; bi++) {
        float v = h[bi] * wfcv;
        #pragma unroll
        for (int off = 16; off > 0; off >>= 1)
            v += __shfl_xor_sync(0xffffffffu, v, off);
        if (j == 0) out[b0 + bi] = v + bfc[0];
    }
}

// ---------------------------------------------------------------------------
extern "C" void kernel_launch(void* const* d_in, const int* in_sizes, int n_in,
                              void* d_out, int out_size)
{
    const float* x   = (const float*)d_in[0];
    const float* Wih = (const float*)d_in[1];
    const float* Whh = (const float*)d_in[2];
    const float* bih = (const float*)d_in[3];
    const float* bhh = (const float*)d_in[4];
    const float* Wfc = (const float*)d_in[5];
    const float* bfc = (const float*)d_in[6];
    float* out = (float*)d_out;

    const int smem1 = 2 * 64 * WTS * sizeof(float);  // 67,584 B
    cudaFuncSetAttribute(k1_inproj, cudaFuncAttributeMaxDynamicSharedMemorySize, smem1);

    dim3 g1(CB / 128, CT);
    k1_inproj<<<g1, 256, smem1>>>(x, Wih, bih, bhh);
    k2_rnn<<<CB / 4, 32>>>(Whh, Wfc, bfc, out);
}